// round 6
// baseline (speedup 1.0000x reference)
#include <cuda_runtime.h>
#include <cuda_bf16.h>
#include <cstdint>
#include <cstddef>

// ---------------------------------------------------------------------------
// HierarchicalMemoryWorker — mma.sync bf16 score GEMM + exact fp32 rerank
// R6: k2 -> 512 threads (16 warps, 4x4 grid, 32x32 warp tiles),
//     3-stage cp.async B ring, single barrier per k-chunk.
// ---------------------------------------------------------------------------

#define NTOK 2048
#define EDIM 512
#define NSEC 8
#define MTOT 2048
#define KDIM 32
#define VDIM 32

// ---- k2 smem layout ----
#define SA_ROWB   1040                     // A row bytes (512 bf16 + 16B pad)
#define SB_ROWB   144                      // B row bytes (64 bf16 + 16B pad)
#define SS_STRIDE 136                      // score row stride in bf16 elems
#define SA_BYTES  (128 * SA_ROWB)          // 133120
#define SB_BYTES  (128 * SB_ROWB)          // 18432 per stage
#define NSTAGE    3
#define SS_OFF    (SA_BYTES + NSTAGE * SB_BYTES)   // 188416
#define SMEM2     (SS_OFF + 128 * 272)             // 223232

// ---- device scratch (no allocation allowed) ----
__device__ float g_xe[NTOK * EDIM];
__device__ float g_tq[NTOK * KDIM];
__device__ float g_w [NTOK * NSEC * 4];
__device__ int   g_ix[NTOK * NSEC * 4];
__device__ __nv_bfloat16 g_xeb[NTOK * EDIM];          // 2 MB bf16 x_emb
__device__ __nv_bfloat16 g_mkb[NSEC * MTOT * EDIM];   // 16 MB bf16 memory_keys

// ---- helpers ----
__device__ __forceinline__ uint32_t smem_u32(const void* p) {
    uint32_t a;
    asm("{ .reg .u64 t; cvta.to.shared.u64 t, %1; cvt.u32.u64 %0, t; }"
        : "=r"(a) : "l"(p));
    return a;
}
#define CP16(d, s) asm volatile("cp.async.ca.shared.global [%0], [%1], 16;" :: "r"(d), "l"(s))
#define CPCOMMIT() asm volatile("cp.async.commit_group;" ::: "memory")
#define CPWAIT1()  asm volatile("cp.async.wait_group 1;" ::: "memory")
#define CPWAIT0()  asm volatile("cp.async.wait_group 0;" ::: "memory")

#define LDM_X4(r0, r1, r2, r3, a) \
    asm volatile("ldmatrix.sync.aligned.m8n8.x4.shared.b16 {%0,%1,%2,%3}, [%4];" \
        : "=r"(r0), "=r"(r1), "=r"(r2), "=r"(r3) : "r"(a))

#define MMA16816(c0, c1, c2, c3, a0, a1, a2, a3, b0, b1) \
    asm volatile("mma.sync.aligned.m16n8k16.row.col.f32.bf16.bf16.f32 " \
        "{%0,%1,%2,%3}, {%4,%5,%6,%7}, {%8,%9}, {%0,%1,%2,%3};" \
        : "+f"(c0), "+f"(c1), "+f"(c2), "+f"(c3) \
        : "r"(a0), "r"(a1), "r"(a2), "r"(a3), "r"(b0), "r"(b1))

// ---------------------------------------------------------------------------
// k1: embed gather + sector softmax + fp32/bf16 x_emb
// ---------------------------------------------------------------------------
__global__ __launch_bounds__(128) void k1_embed(
    const int* __restrict__ x, const float* __restrict__ emb,
    const float* __restrict__ skeys, float* __restrict__ outSD)
{
    const int t = blockIdx.x, tid = threadIdx.x;
    const int lane = tid & 31, wid = tid >> 5;
    __shared__ float sred[NSEC][4];

    const int xi = x[t];
    float4 ev = *(const float4*)&emb[(size_t)xi * EDIM + tid * 4];
    *(float4*)&g_xe[(size_t)t * EDIM + tid * 4] = ev;
    {
        __nv_bfloat162 p0 = __floats2bfloat162_rn(ev.x, ev.y);
        __nv_bfloat162 p1 = __floats2bfloat162_rn(ev.z, ev.w);
        uint2 u; u.x = *(uint32_t*)&p0; u.y = *(uint32_t*)&p1;
        *(uint2*)&g_xeb[(size_t)t * EDIM + tid * 4] = u;
    }

    float p[NSEC];
#pragma unroll
    for (int n = 0; n < NSEC; n++) {
        float4 kv = *(const float4*)&skeys[n * EDIM + tid * 4];
        p[n] = ev.x*kv.x + ev.y*kv.y + ev.z*kv.z + ev.w*kv.w;
    }
#pragma unroll
    for (int n = 0; n < NSEC; n++)
#pragma unroll
        for (int o = 16; o > 0; o >>= 1)
            p[n] += __shfl_xor_sync(0xffffffffu, p[n], o);
    if (lane == 0)
#pragma unroll
        for (int n = 0; n < NSEC; n++) sred[n][wid] = p[n];
    __syncthreads();
    if (tid == 0) {
        float s[NSEC], mx = -1e30f, sum = 0.f;
#pragma unroll
        for (int n = 0; n < NSEC; n++) {
            s[n] = sred[n][0] + sred[n][1] + sred[n][2] + sred[n][3];
            mx = fmaxf(mx, s[n]);
        }
#pragma unroll
        for (int n = 0; n < NSEC; n++) { s[n] = expf(s[n] - mx); sum += s[n]; }
#pragma unroll
        for (int n = 0; n < NSEC; n++) outSD[t * NSEC + n] = s[n] / sum;
    }
}

// ---------------------------------------------------------------------------
// mkb_conv: memory_keys fp32 -> bf16 linear (8 elems / thread, 4096 blocks)
// ---------------------------------------------------------------------------
__global__ __launch_bounds__(256) void mkb_conv(const float* __restrict__ mkeys)
{
    const size_t gi = (size_t)blockIdx.x * 256 + threadIdx.x;
    const float4* s = (const float4*)mkeys + gi * 2;
    float4 a = s[0], b = s[1];
    __nv_bfloat162 p0 = __floats2bfloat162_rn(a.x, a.y);
    __nv_bfloat162 p1 = __floats2bfloat162_rn(a.z, a.w);
    __nv_bfloat162 p2 = __floats2bfloat162_rn(b.x, b.y);
    __nv_bfloat162 p3 = __floats2bfloat162_rn(b.z, b.w);
    uint4 u;
    u.x = *(uint32_t*)&p0; u.y = *(uint32_t*)&p1;
    u.z = *(uint32_t*)&p2; u.w = *(uint32_t*)&p3;
    ((uint4*)g_mkb)[gi] = u;
}

// ---------------------------------------------------------------------------
// k1b: token query GEMM  tq[T,32] = xe[T,512] @ Wq[512,32] + bq
// ---------------------------------------------------------------------------
#define XSTR 68
__global__ __launch_bounds__(256) void k1b_tq(
    const float* __restrict__ Wq, const float* __restrict__ bq)
{
    extern __shared__ float s1b[];
    float* sWq = s1b;                   // 16384 floats
    float* sxe = s1b + EDIM * KDIM;     // 32 * XSTR
    const int tid = threadIdx.x, tb = blockIdx.x * 32;
    const int row = tid & 31, h = tid >> 5;

    const float4* Wq4 = (const float4*)Wq;
#pragma unroll
    for (int i = 0; i < 16; i++)
        ((float4*)sWq)[i * 256 + tid] = Wq4[i * 256 + tid];

    float4 acc = *(const float4*)&bq[h * 4];
    for (int kc = 0; kc < EDIM; kc += 64) {
        __syncthreads();
        {
            const int lr = tid >> 3, lk = (tid & 7) * 8;
            const float* src = &g_xe[(size_t)(tb + lr) * EDIM + kc + lk];
            float4 a = *(const float4*)src, b = *(const float4*)(src + 4);
            float* d = &sxe[lr * XSTR + lk];
            d[0]=a.x; d[1]=a.y; d[2]=a.z; d[3]=a.w;
            d[4]=b.x; d[5]=b.y; d[6]=b.z; d[7]=b.w;
        }
        __syncthreads();
#pragma unroll 8
        for (int k = 0; k < 64; k++) {
            float a = sxe[row * XSTR + k];
            float4 wv = *(const float4*)&sWq[(kc + k) * KDIM + h * 4];
            acc.x += a * wv.x; acc.y += a * wv.y;
            acc.z += a * wv.z; acc.w += a * wv.w;
        }
    }
    *(float4*)&g_tq[(size_t)(tb + row) * KDIM + h * 4] = acc;
}

// ---------------------------------------------------------------------------
// k2: mma.sync bf16 score GEMM + streaming top-8 + exact fp32 rerank
// grid (16, 8), 512 threads = 16 warps (4 tokQuarter x 4 memQuarter)
// ---------------------------------------------------------------------------
__global__ __launch_bounds__(512, 1) void k2_scores(const float* __restrict__ mkeys)
{
    extern __shared__ unsigned char sm2[];
    __nv_bfloat16* sS = (__nv_bfloat16*)(sm2 + SS_OFF);
    __shared__ int scand[128 * 8];

    const int tid = threadIdx.x, wid = tid >> 5, lane = tid & 31;
    const int tt = blockIdx.x, n = blockIdx.y, tb = tt * 128;
    const int warpM = wid & 3, warpN = wid >> 2;

    const uint32_t aAddr = smem_u32(sm2);
    const uint32_t bAddr0 = aAddr + SA_BYTES;

    // ---- A: 128 x 512 bf16 -> smem (padded rows), one cp.async group ----
    {
        const __nv_bfloat16* Asrc = g_xeb + (size_t)tb * EDIM;
#pragma unroll
        for (int it = 0; it < 16; it++) {
            int idx = it * 512 + tid;       // 0..8191
            int r = idx >> 6, c = idx & 63;
            CP16(aAddr + r * SA_ROWB + c * 16, Asrc + (size_t)r * EDIM + c * 8);
        }
        CPCOMMIT();
    }

    const __nv_bfloat16* Bn = g_mkb + (size_t)n * MTOT * EDIM;
    auto issueB = [&](int ck) {
        const int chunk = ck >> 3, kb = ck & 7;
        const __nv_bfloat16* src = Bn + (size_t)(chunk * 128) * EDIM + kb * 64;
        const uint32_t dst = bAddr0 + (ck % NSTAGE) * SB_BYTES;
#pragma unroll
        for (int it = 0; it < 2; it++) {
            int idx = it * 512 + tid;       // 0..1023
            int r = idx >> 3, c = idx & 7;
            CP16(dst + r * SB_ROWB + c * 16, src + (size_t)r * EDIM + c * 8);
        }
        CPCOMMIT();
    };
    issueB(0);
    issueB(1);

    // top-8 state (tid < 128 owns token tb+tid)
    float vt[8]; int ixt[8];
#pragma unroll
    for (int i = 0; i < 8; i++) { vt[i] = -3e38f; ixt[i] = 0; }

    float acc[2][4][4];
#pragma unroll
    for (int i = 0; i < 2; i++)
#pragma unroll
        for (int j = 0; j < 4; j++)
#pragma unroll
            for (int r = 0; r < 4; r++) acc[i][j][r] = 0.f;

    // ldmatrix lane address components (32x32 warp tile)
    const int aRow = warpM * 32 + (lane & 15);                   // + i*16
    const int aKof = (lane >> 4) * 8;                            // + k0
    const int bRow = warpN * 32 + (lane & 7) + (lane >> 4) * 8;  // + jp*16
    const int bKof = ((lane >> 3) & 1) * 8;                      // + k0

    for (int ck = 0; ck < 128; ck++) {
        const int kb = ck & 7;
        if (ck == 127) { CPWAIT0(); } else { CPWAIT1(); }
        __syncthreads();
        if (ck + 2 < 128) issueB(ck + 2);

        const uint32_t bBuf = bAddr0 + (ck % NSTAGE) * SB_BYTES;
#pragma unroll
        for (int s = 0; s < 4; s++) {
            const int k0 = s * 16;
            uint32_t a[2][4];
#pragma unroll
            for (int i = 0; i < 2; i++) {
                uint32_t ad = aAddr + (aRow + i * 16) * SA_ROWB
                            + (kb * 64 + k0 + aKof) * 2;
                LDM_X4(a[i][0], a[i][1], a[i][2], a[i][3], ad);
            }
            uint32_t b[4][2];
#pragma unroll
            for (int jp = 0; jp < 2; jp++) {
                uint32_t bd = bBuf + (bRow + jp * 16) * SB_ROWB
                            + (k0 + bKof) * 2;
                LDM_X4(b[jp*2][0], b[jp*2][1], b[jp*2+1][0], b[jp*2+1][1], bd);
            }
#pragma unroll
            for (int i = 0; i < 2; i++)
#pragma unroll
                for (int j = 0; j < 4; j++)
                    MMA16816(acc[i][j][0], acc[i][j][1], acc[i][j][2], acc[i][j][3],
                             a[i][0], a[i][1], a[i][2], a[i][3],
                             b[j][0], b[j][1]);
        }

        if (kb == 7) {
            // ---- epilogue: dump scores (bf16) + streaming top-8 scan ----
            const int row0 = warpM * 32 + (lane >> 2);
            const int col0 = warpN * 32 + (lane & 3) * 2;
            __syncthreads();   // all warps done reading B stage (and prior sS scan)
#pragma unroll
            for (int i = 0; i < 2; i++)
#pragma unroll
                for (int j = 0; j < 4; j++) {
                    __nv_bfloat162 lo =
                        __floats2bfloat162_rn(acc[i][j][0], acc[i][j][1]);
                    __nv_bfloat162 hi =
                        __floats2bfloat162_rn(acc[i][j][2], acc[i][j][3]);
                    *(uint32_t*)&sS[(row0 + i * 16) * SS_STRIDE + col0 + j * 8] =
                        *(uint32_t*)&lo;
                    *(uint32_t*)&sS[(row0 + i * 16 + 8) * SS_STRIDE + col0 + j * 8] =
                        *(uint32_t*)&hi;
                    acc[i][j][0] = acc[i][j][1] = acc[i][j][2] = acc[i][j][3] = 0.f;
                }
            __syncthreads();
            if (tid < 128) {
                const int mbase = (ck >> 3) * 128;
                const __nv_bfloat16* srow = sS + tid * SS_STRIDE;
#pragma unroll 2
                for (int c0 = 0; c0 < 128; c0 += 8) {
                    uint4 u = *(const uint4*)(srow + c0);
                    const __nv_bfloat162* hp = (const __nv_bfloat162*)&u;
#pragma unroll
                    for (int p = 0; p < 4; p++) {
                        float f0 = __bfloat162float(__low2bfloat16(hp[p]));
                        float f1 = __bfloat162float(__high2bfloat16(hp[p]));
#pragma unroll
                        for (int h = 0; h < 2; h++) {
                            float sv = h ? f1 : f0;
                            if (sv > vt[7]) {
                                vt[7] = sv; ixt[7] = mbase + c0 + p * 2 + h;
#pragma unroll
                                for (int q = 7; q > 0; q--) {
                                    if (vt[q] > vt[q-1]) {
                                        float a2 = vt[q]; vt[q] = vt[q-1]; vt[q-1] = a2;
                                        int b2 = ixt[q]; ixt[q] = ixt[q-1]; ixt[q-1] = b2;
                                    }
                                }
                            }
                        }
                    }
                }
            }
        }
    }

    if (tid < 128)
#pragma unroll
        for (int c = 0; c < 8; c++) scand[tid * 8 + c] = ixt[c];
    __syncthreads();

    // ---- exact fp32 rerank: 16 warps x 8 tokens, lane-split over E ----
    for (int ti = 0; ti < 8; ti++) {
        const int tl = wid * 8 + ti, t = tb + tl;
        const float* xr = g_xe + (size_t)t * EDIM + lane * 16;
        float4 x0 = *(const float4*)xr,       x1 = *(const float4*)(xr + 4);
        float4 x2 = *(const float4*)(xr + 8), x3 = *(const float4*)(xr + 12);
        float sc[8]; int ci[8];
#pragma unroll
        for (int c = 0; c < 8; c++) {
            ci[c] = scand[tl * 8 + c];
            const float* mr =
                mkeys + ((size_t)n * MTOT + ci[c]) * EDIM + lane * 16;
            float4 m0 = *(const float4*)mr,       m1 = *(const float4*)(mr + 4);
            float4 m2 = *(const float4*)(mr + 8), m3 = *(const float4*)(mr + 12);
            float d =            x0.x*m0.x;  d = fmaf(x0.y, m0.y, d);
            d = fmaf(x0.z, m0.z, d); d = fmaf(x0.w, m0.w, d);
            d = fmaf(x1.x, m1.x, d); d = fmaf(x1.y, m1.y, d);
            d = fmaf(x1.z, m1.z, d); d = fmaf(x1.w, m1.w, d);
            d = fmaf(x2.x, m2.x, d); d = fmaf(x2.y, m2.y, d);
            d = fmaf(x2.z, m2.z, d); d = fmaf(x2.w, m2.w, d);
            d = fmaf(x3.x, m3.x, d); d = fmaf(x3.y, m3.y, d);
            d = fmaf(x3.z, m3.z, d); d = fmaf(x3.w, m3.w, d);
#pragma unroll
            for (int o = 16; o > 0; o >>= 1)
                d += __shfl_xor_sync(0xffffffffu, d, o);
            sc[c] = d;
        }
        unsigned used = 0;
        float w4[4]; int id4[4];
#pragma unroll
        for (int s4 = 0; s4 < 4; s4++) {
            float bv = -3e38f; int bi = 0x7fffffff, bc = 0;
#pragma unroll
            for (int c = 0; c < 8; c++) {
                if (!((used >> c) & 1)) {
                    bool bet = (sc[c] > bv) || (sc[c] == bv && ci[c] < bi);
                    if (bet) { bv = sc[c]; bi = ci[c]; bc = c; }
                }
            }
            used |= 1u << bc; w4[s4] = bv; id4[s4] = bi;
        }
        if (lane == 0) {
            float e1 = expf(w4[1] - w4[0]);
            float e2 = expf(w4[2] - w4[0]);
            float e3 = expf(w4[3] - w4[0]);
            float ss = 1.f + e1 + e2 + e3;
            const int base = t * (NSEC * 4) + n * 4;
            g_w[base + 0] = 1.f / ss; g_ix[base + 0] = id4[0];
            g_w[base + 1] = e1 / ss;  g_ix[base + 1] = id4[1];
            g_w[base + 2] = e2 / ss;  g_ix[base + 2] = id4[2];
            g_w[base + 3] = e3 / ss;  g_ix[base + 3] = id4[3];
        }
    }
}

// ---------------------------------------------------------------------------
// k3: knowledge gather + matvec + sector mix + proj + residual + LayerNorm
// ---------------------------------------------------------------------------
__global__ __launch_bounds__(128) void k3_output(
    const float* __restrict__ knowledge, const float* __restrict__ Wo,
    const float* __restrict__ bo, const float* __restrict__ gamma,
    const float* __restrict__ beta, float* __restrict__ out)
{
    const int t = blockIdx.x, tid = threadIdx.x;
    const int lane = tid & 31, wid = tid >> 5;

    __shared__ float q[KDIM];
    __shared__ float sd[NSEC];
    __shared__ float fpart[4][VDIM];
    __shared__ float fin[VDIM];
    __shared__ float rs[4], rs2[4];
    __shared__ float mv[2];

    if (tid < KDIM) q[tid] = g_tq[t * KDIM + tid];
    if (tid < NSEC) sd[tid] = out[(size_t)NTOK * EDIM + t * NSEC + tid];
    __syncthreads();

    float facc = 0.f;
#pragma unroll
    for (int n = 0; n < NSEC; n++) {
        const int p = t * (NSEC * 4) + n * 4 + wid;
        const float wgt = g_w[p];
        const int   mi  = g_ix[p];
        const float* kn = knowledge + ((size_t)n * MTOT + mi) * (KDIM * VDIM);
        float r = 0.f;
#pragma unroll
        for (int d = 0; d < KDIM; d++)
            r += q[d] * kn[d * VDIM + lane];
        facc += sd[n] * wgt * r;
    }
    fpart[wid][lane] = facc;
    __syncthreads();
    if (tid < VDIM)
        fin[tid] = fpart[0][tid] + fpart[1][tid] + fpart[2][tid] + fpart[3][tid];
    __syncthreads();

    float4 accv = *(const float4*)&bo[tid * 4];
#pragma unroll
    for (int v = 0; v < VDIM; v++) {
        float fv = fin[v];
        float4 wv = *(const float4*)&Wo[v * EDIM + tid * 4];
        accv.x += fv * wv.x; accv.y += fv * wv.y;
        accv.z += fv * wv.z; accv.w += fv * wv.w;
    }
    float4 xv = *(const float4*)&g_xe[(size_t)t * EDIM + tid * 4];
    float4 h;
    h.x = xv.x + accv.x; h.y = xv.y + accv.y;
    h.z = xv.z + accv.z; h.w = xv.w + accv.w;

    float s  = h.x + h.y + h.z + h.w;
    float s2 = h.x*h.x + h.y*h.y + h.z*h.z + h.w*h.w;
#pragma unroll
    for (int o = 16; o > 0; o >>= 1) {
        s  += __shfl_xor_sync(0xffffffffu, s,  o);
        s2 += __shfl_xor_sync(0xffffffffu, s2, o);
    }
    if (lane == 0) { rs[wid] = s; rs2[wid] = s2; }
    __syncthreads();
    if (tid == 0) {
        float S  = rs[0] + rs[1] + rs[2] + rs[3];
        float S2 = rs2[0] + rs2[1] + rs2[2] + rs2[3];
        float mu  = S / (float)EDIM;
        float var = S2 / (float)EDIM - mu * mu;
        mv[0] = mu; mv[1] = rsqrtf(var + 1e-5f);
    }
    __syncthreads();
    const float mu = mv[0], rstd = mv[1];

    float4 gv = *(const float4*)&gamma[tid * 4];
    float4 bv = *(const float4*)&beta[tid * 4];
    float4 ov;
    ov.x = (h.x - mu) * rstd * gv.x + bv.x;
    ov.y = (h.y - mu) * rstd * gv.y + bv.y;
    ov.z = (h.z - mu) * rstd * gv.z + bv.z;
    ov.w = (h.w - mu) * rstd * gv.w + bv.w;
    *(float4*)&out[(size_t)t * EDIM + tid * 4] = ov;
}

// ---------------------------------------------------------------------------
extern "C" void kernel_launch(void* const* d_in, const int* in_sizes, int n_in,
                              void* d_out, int out_size)
{
    const int off = (n_in >= 12 && in_sizes[1] == 1) ? 1 : 0;

    const int*   x     = (const int*)  d_in[0];
    const float* emb   = (const float*)d_in[1 + off];
    const float* skeys = (const float*)d_in[2 + off];
    const float* mkeys = (const float*)d_in[3 + off];
    const float* knowl = (const float*)d_in[4 + off];
    const float* Wq    = (const float*)d_in[5 + off];
    const float* bq    = (const float*)d_in[6 + off];
    const float* Wo    = (const float*)d_in[7 + off];
    const float* bo    = (const float*)d_in[8 + off];
    const float* gamma = (const float*)d_in[9 + off];
    const float* beta  = (const float*)d_in[10 + off];
    float* out = (float*)d_out;
    (void)out_size;

    cudaFuncSetAttribute(k2_scores,
                         cudaFuncAttributeMaxDynamicSharedMemorySize, SMEM2);
    cudaFuncSetAttribute(k1b_tq,
                         cudaFuncAttributeMaxDynamicSharedMemorySize,
                         (EDIM * KDIM + 32 * XSTR) * 4);

    k1_embed<<<NTOK, 128>>>(x, emb, skeys, out + (size_t)NTOK * EDIM);
    mkb_conv<<<4096, 256>>>(mkeys);
    k1b_tq  <<<64, 256, (EDIM * KDIM + 32 * XSTR) * 4>>>(Wq, bq);
    k2_scores<<<dim3(16, 8), 512, SMEM2>>>(mkeys);
    k3_output<<<NTOK, 128>>>(knowl, Wo, bo, gamma, beta, out);
}

// round 7
// speedup vs baseline: 1.0491x; 1.0491x over previous
#include <cuda_runtime.h>
#include <cuda_bf16.h>
#include <cstdint>
#include <cstddef>

// ---------------------------------------------------------------------------
// HierarchicalMemoryWorker — mma.sync bf16 score GEMM + exact fp32 rerank
// R7: 8 warps / 64x32 warp tiles, XOR-swizzled smem (conflict-free ldmatrix),
//     4-stage B ring w/ one barrier per 2 k-chunks, register-double-buffered
//     fragments.
// ---------------------------------------------------------------------------

#define NTOK 2048
#define EDIM 512
#define NSEC 8
#define MTOT 2048
#define KDIM 32
#define VDIM 32

// ---- k2 smem layout ----
#define SA_BYTES  (128 * 1024)             // A: 128 rows x 1024B, swizzled
#define SB_BYTES  (128 * 128)              // B stage: 128 rows x 128B, swizzled
#define NSTAGE    4
#define SS_OFF    (SA_BYTES + NSTAGE * SB_BYTES)   // 196608
#define SS_STRIDE 136                      // score row stride (bf16 elems)
#define SMEM2     (SS_OFF + 128 * SS_STRIDE * 2)   // 231424

// ---- device scratch (no allocation allowed) ----
__device__ float g_xe[NTOK * EDIM];
__device__ float g_tq[NTOK * KDIM];
__device__ float g_w [NTOK * NSEC * 4];
__device__ int   g_ix[NTOK * NSEC * 4];
__device__ __nv_bfloat16 g_xeb[NTOK * EDIM];          // 2 MB bf16 x_emb
__device__ __nv_bfloat16 g_mkb[NSEC * MTOT * EDIM];   // 16 MB bf16 memory_keys

// ---- helpers ----
__device__ __forceinline__ uint32_t smem_u32(const void* p) {
    uint32_t a;
    asm("{ .reg .u64 t; cvta.to.shared.u64 t, %1; cvt.u32.u64 %0, t; }"
        : "=r"(a) : "l"(p));
    return a;
}
#define CP16(d, s) asm volatile("cp.async.ca.shared.global [%0], [%1], 16;" :: "r"(d), "l"(s))
#define CPCOMMIT() asm volatile("cp.async.commit_group;" ::: "memory")
#define CPWAIT0()  asm volatile("cp.async.wait_group 0;" ::: "memory")

#define LDM_X4(r0, r1, r2, r3, a) \
    asm volatile("ldmatrix.sync.aligned.m8n8.x4.shared.b16 {%0,%1,%2,%3}, [%4];" \
        : "=r"(r0), "=r"(r1), "=r"(r2), "=r"(r3) : "r"(a))

#define MMA16816(c0, c1, c2, c3, a0, a1, a2, a3, b0, b1) \
    asm volatile("mma.sync.aligned.m16n8k16.row.col.f32.bf16.bf16.f32 " \
        "{%0,%1,%2,%3}, {%4,%5,%6,%7}, {%8,%9}, {%0,%1,%2,%3};" \
        : "+f"(c0), "+f"(c1), "+f"(c2), "+f"(c3) \
        : "r"(a0), "r"(a1), "r"(a2), "r"(a3), "r"(b0), "r"(b1))

// ---------------------------------------------------------------------------
// k1: embed gather + sector softmax + fp32/bf16 x_emb
// ---------------------------------------------------------------------------
__global__ __launch_bounds__(128) void k1_embed(
    const int* __restrict__ x, const float* __restrict__ emb,
    const float* __restrict__ skeys, float* __restrict__ outSD)
{
    const int t = blockIdx.x, tid = threadIdx.x;
    const int lane = tid & 31, wid = tid >> 5;
    __shared__ float sred[NSEC][4];

    const int xi = x[t];
    float4 ev = *(const float4*)&emb[(size_t)xi * EDIM + tid * 4];
    *(float4*)&g_xe[(size_t)t * EDIM + tid * 4] = ev;
    {
        __nv_bfloat162 p0 = __floats2bfloat162_rn(ev.x, ev.y);
        __nv_bfloat162 p1 = __floats2bfloat162_rn(ev.z, ev.w);
        uint2 u; u.x = *(uint32_t*)&p0; u.y = *(uint32_t*)&p1;
        *(uint2*)&g_xeb[(size_t)t * EDIM + tid * 4] = u;
    }

    float p[NSEC];
#pragma unroll
    for (int n = 0; n < NSEC; n++) {
        float4 kv = *(const float4*)&skeys[n * EDIM + tid * 4];
        p[n] = ev.x*kv.x + ev.y*kv.y + ev.z*kv.z + ev.w*kv.w;
    }
#pragma unroll
    for (int n = 0; n < NSEC; n++)
#pragma unroll
        for (int o = 16; o > 0; o >>= 1)
            p[n] += __shfl_xor_sync(0xffffffffu, p[n], o);
    if (lane == 0)
#pragma unroll
        for (int n = 0; n < NSEC; n++) sred[n][wid] = p[n];
    __syncthreads();
    if (tid == 0) {
        float s[NSEC], mx = -1e30f, sum = 0.f;
#pragma unroll
        for (int n = 0; n < NSEC; n++) {
            s[n] = sred[n][0] + sred[n][1] + sred[n][2] + sred[n][3];
            mx = fmaxf(mx, s[n]);
        }
#pragma unroll
        for (int n = 0; n < NSEC; n++) { s[n] = expf(s[n] - mx); sum += s[n]; }
#pragma unroll
        for (int n = 0; n < NSEC; n++) outSD[t * NSEC + n] = s[n] / sum;
    }
}

// ---------------------------------------------------------------------------
// mkb_conv: memory_keys fp32 -> bf16 linear (8 elems / thread, 4096 blocks)
// ---------------------------------------------------------------------------
__global__ __launch_bounds__(256) void mkb_conv(const float* __restrict__ mkeys)
{
    const size_t gi = (size_t)blockIdx.x * 256 + threadIdx.x;
    const float4* s = (const float4*)mkeys + gi * 2;
    float4 a = s[0], b = s[1];
    __nv_bfloat162 p0 = __floats2bfloat162_rn(a.x, a.y);
    __nv_bfloat162 p1 = __floats2bfloat162_rn(a.z, a.w);
    __nv_bfloat162 p2 = __floats2bfloat162_rn(b.x, b.y);
    __nv_bfloat162 p3 = __floats2bfloat162_rn(b.z, b.w);
    uint4 u;
    u.x = *(uint32_t*)&p0; u.y = *(uint32_t*)&p1;
    u.z = *(uint32_t*)&p2; u.w = *(uint32_t*)&p3;
    ((uint4*)g_mkb)[gi] = u;
}

// ---------------------------------------------------------------------------
// k1b: token query GEMM  tq[T,32] = xe[T,512] @ Wq[512,32] + bq
// ---------------------------------------------------------------------------
#define XSTR 68
__global__ __launch_bounds__(256) void k1b_tq(
    const float* __restrict__ Wq, const float* __restrict__ bq)
{
    extern __shared__ float s1b[];
    float* sWq = s1b;                   // 16384 floats
    float* sxe = s1b + EDIM * KDIM;     // 32 * XSTR
    const int tid = threadIdx.x, tb = blockIdx.x * 32;
    const int row = tid & 31, h = tid >> 5;

    const float4* Wq4 = (const float4*)Wq;
#pragma unroll
    for (int i = 0; i < 16; i++)
        ((float4*)sWq)[i * 256 + tid] = Wq4[i * 256 + tid];

    float4 acc = *(const float4*)&bq[h * 4];
    for (int kc = 0; kc < EDIM; kc += 64) {
        __syncthreads();
        {
            const int lr = tid >> 3, lk = (tid & 7) * 8;
            const float* src = &g_xe[(size_t)(tb + lr) * EDIM + kc + lk];
            float4 a = *(const float4*)src, b = *(const float4*)(src + 4);
            float* d = &sxe[lr * XSTR + lk];
            d[0]=a.x; d[1]=a.y; d[2]=a.z; d[3]=a.w;
            d[4]=b.x; d[5]=b.y; d[6]=b.z; d[7]=b.w;
        }
        __syncthreads();
#pragma unroll 8
        for (int k = 0; k < 64; k++) {
            float a = sxe[row * XSTR + k];
            float4 wv = *(const float4*)&sWq[(kc + k) * KDIM + h * 4];
            acc.x += a * wv.x; acc.y += a * wv.y;
            acc.z += a * wv.z; acc.w += a * wv.w;
        }
    }
    *(float4*)&g_tq[(size_t)(tb + row) * KDIM + h * 4] = acc;
}

// ---------------------------------------------------------------------------
// k2: mma.sync bf16 score GEMM + streaming top-8 + exact fp32 rerank
// grid (16, 8), 256 threads = 8 warps (2 tokHalf x 4 memQuarter), 64x32 tiles
// ---------------------------------------------------------------------------
__global__ __launch_bounds__(256, 1) void k2_scores(const float* __restrict__ mkeys)
{
    extern __shared__ unsigned char sm2[];
    __nv_bfloat16* sS = (__nv_bfloat16*)(sm2 + SS_OFF);

    const int tid = threadIdx.x, wid = tid >> 5, lane = tid & 31;
    const int tt = blockIdx.x, n = blockIdx.y, tb = tt * 128;
    const int warpM = wid & 1, warpN = wid >> 1;

    const uint32_t aAddr = smem_u32(sm2);
    const uint32_t bAddr0 = aAddr + SA_BYTES;

    // ---- A: 128 x 512 bf16 -> swizzled smem (row 1024B, c16 ^= r&7) ----
    {
        const __nv_bfloat16* Asrc = g_xeb + (size_t)tb * EDIM;
#pragma unroll
        for (int it = 0; it < 32; it++) {
            int idx = it * 256 + tid;       // 0..8191
            int r = idx >> 6, c = idx & 63;
            CP16(aAddr + (r << 10) + ((c ^ (r & 7)) << 4),
                 Asrc + (size_t)r * EDIM + c * 8);
        }
        CPCOMMIT();
    }

    const __nv_bfloat16* Bn = g_mkb + (size_t)n * MTOT * EDIM;
    auto issueB = [&](int ck) {
        const int chunk = ck >> 3, kb = ck & 7;
        const __nv_bfloat16* src = Bn + (size_t)(chunk * 128) * EDIM + kb * 64;
        const uint32_t dst = bAddr0 + (ck & 3) * SB_BYTES;
#pragma unroll
        for (int it = 0; it < 4; it++) {
            int idx = it * 256 + tid;       // 0..1023
            int r = idx >> 3, c = idx & 7;
            CP16(dst + (r << 7) + ((c ^ (r & 7)) << 4),
                 src + (size_t)r * EDIM + c * 8);
        }
        CPCOMMIT();
    };
    issueB(0);
    issueB(1);

    // top-8 state (tid < 128 owns token tb+tid)
    float vt[8]; int ixt[8];
#pragma unroll
    for (int i = 0; i < 8; i++) { vt[i] = -3e38f; ixt[i] = 0; }

    float acc[4][4][4];
#pragma unroll
    for (int i = 0; i < 4; i++)
#pragma unroll
        for (int j = 0; j < 4; j++)
#pragma unroll
            for (int r = 0; r < 4; r++) acc[i][j][r] = 0.f;

    // ldmatrix lane constants
    const int xr7  = lane & 7;                                  // swizzle XOR
    const int aRowL = warpM * 64 + (lane & 15);                 // + i*16
    const int aHi   = lane >> 4;                                // 16B col half
    const int bRowL = warpN * 32 + (lane & 7) + ((lane >> 4) << 3); // + jp*16
    const int bHalf = (lane >> 3) & 1;

    uint32_t fa[2][4][4], fb[2][4][2];

    auto loadFrags = [&](int buf, int ckk, int s) {
        const int kb = ckk & 7;
        const uint32_t bBuf = bAddr0 + (ckk & 3) * SB_BYTES;
#pragma unroll
        for (int i = 0; i < 4; i++) {
            int c16 = kb * 8 + s * 2 + aHi;
            uint32_t ad = aAddr + ((aRowL + i * 16) << 10) + ((c16 ^ xr7) << 4);
            LDM_X4(fa[buf][i][0], fa[buf][i][1], fa[buf][i][2], fa[buf][i][3], ad);
        }
#pragma unroll
        for (int jp = 0; jp < 2; jp++) {
            int c16 = s * 2 + bHalf;
            uint32_t bd = bBuf + ((bRowL + jp * 16) << 7) + ((c16 ^ xr7) << 4);
            LDM_X4(fb[buf][jp*2][0], fb[buf][jp*2][1],
                   fb[buf][jp*2+1][0], fb[buf][jp*2+1][1], bd);
        }
    };

    for (int ck0 = 0; ck0 < 128; ck0 += 2) {
        CPWAIT0();
        __syncthreads();
        if (ck0 + 2 < 128) { issueB(ck0 + 2); issueB(ck0 + 3); }

        loadFrags(0, ck0, 0);
#pragma unroll
        for (int step = 0; step < 8; step++) {
            const int cur = step & 1, nxt = cur ^ 1;
            if (step < 7) {
                const int ns = step + 1;
                loadFrags(nxt, ck0 + (ns >> 2), ns & 3);
            }
#pragma unroll
            for (int i = 0; i < 4; i++)
#pragma unroll
                for (int j = 0; j < 4; j++)
                    MMA16816(acc[i][j][0], acc[i][j][1], acc[i][j][2], acc[i][j][3],
                             fa[cur][i][0], fa[cur][i][1], fa[cur][i][2], fa[cur][i][3],
                             fb[cur][j][0], fb[cur][j][1]);
        }

        if ((ck0 & 7) == 6) {
            // ---- epilogue: dump scores (bf16) + streaming top-8 scan ----
            const int row0 = warpM * 64 + (lane >> 2);
            const int col0 = warpN * 32 + (lane & 3) * 2;
#pragma unroll
            for (int i = 0; i < 4; i++)
#pragma unroll
                for (int j = 0; j < 4; j++) {
                    __nv_bfloat162 lo =
                        __floats2bfloat162_rn(acc[i][j][0], acc[i][j][1]);
                    __nv_bfloat162 hi =
                        __floats2bfloat162_rn(acc[i][j][2], acc[i][j][3]);
                    *(uint32_t*)&sS[(row0 + i * 16) * SS_STRIDE + col0 + j * 8] =
                        *(uint32_t*)&lo;
                    *(uint32_t*)&sS[(row0 + i * 16 + 8) * SS_STRIDE + col0 + j * 8] =
                        *(uint32_t*)&hi;
                    acc[i][j][0] = acc[i][j][1] = acc[i][j][2] = acc[i][j][3] = 0.f;
                }
            __syncthreads();
            if (tid < 128) {
                const int mbase = (ck0 >> 3) * 128;
                const __nv_bfloat16* srow = sS + tid * SS_STRIDE;
#pragma unroll 2
                for (int c0 = 0; c0 < 128; c0 += 8) {
                    uint4 u = *(const uint4*)(srow + c0);
                    const __nv_bfloat162* hp = (const __nv_bfloat162*)&u;
#pragma unroll
                    for (int p = 0; p < 4; p++) {
                        float f0 = __bfloat162float(__low2bfloat16(hp[p]));
                        float f1 = __bfloat162float(__high2bfloat16(hp[p]));
#pragma unroll
                        for (int h = 0; h < 2; h++) {
                            float sv = h ? f1 : f0;
                            if (sv > vt[7]) {
                                vt[7] = sv; ixt[7] = mbase + c0 + p * 2 + h;
#pragma unroll
                                for (int q = 7; q > 0; q--) {
                                    if (vt[q] > vt[q-1]) {
                                        float a2 = vt[q]; vt[q] = vt[q-1]; vt[q-1] = a2;
                                        int b2 = ixt[q]; ixt[q] = ixt[q-1]; ixt[q-1] = b2;
                                    }
                                }
                            }
                        }
                    }
                }
            }
            // next pair's top-of-loop barrier orders scan before reuse
        }
    }

    // scand overlays the (now dead) score tile region
    __syncthreads();
    int* scand = (int*)sS;
    if (tid < 128)
#pragma unroll
        for (int c = 0; c < 8; c++) scand[tid * 8 + c] = ixt[c];
    __syncthreads();

    // ---- exact fp32 rerank: 8 warps x 16 tokens, lane-split over E ----
    for (int ti = 0; ti < 16; ti++) {
        const int tl = wid * 16 + ti, t = tb + tl;
        const float* xr = g_xe + (size_t)t * EDIM + lane * 16;
        float4 x0 = *(const float4*)xr,       x1 = *(const float4*)(xr + 4);
        float4 x2 = *(const float4*)(xr + 8), x3 = *(const float4*)(xr + 12);
        float sc[8]; int ci[8];
#pragma unroll
        for (int c = 0; c < 8; c++) {
            ci[c] = scand[tl * 8 + c];
            const float* mr =
                mkeys + ((size_t)n * MTOT + ci[c]) * EDIM + lane * 16;
            float4 m0 = *(const float4*)mr,       m1 = *(const float4*)(mr + 4);
            float4 m2 = *(const float4*)(mr + 8), m3 = *(const float4*)(mr + 12);
            float d =            x0.x*m0.x;  d = fmaf(x0.y, m0.y, d);
            d = fmaf(x0.z, m0.z, d); d = fmaf(x0.w, m0.w, d);
            d = fmaf(x1.x, m1.x, d); d = fmaf(x1.y, m1.y, d);
            d = fmaf(x1.z, m1.z, d); d = fmaf(x1.w, m1.w, d);
            d = fmaf(x2.x, m2.x, d); d = fmaf(x2.y, m2.y, d);
            d = fmaf(x2.z, m2.z, d); d = fmaf(x2.w, m2.w, d);
            d = fmaf(x3.x, m3.x, d); d = fmaf(x3.y, m3.y, d);
            d = fmaf(x3.z, m3.z, d); d = fmaf(x3.w, m3.w, d);
#pragma unroll
            for (int o = 16; o > 0; o >>= 1)
                d += __shfl_xor_sync(0xffffffffu, d, o);
            sc[c] = d;
        }
        unsigned used = 0;
        float w4[4]; int id4[4];
#pragma unroll
        for (int s4 = 0; s4 < 4; s4++) {
            float bv = -3e38f; int bi = 0x7fffffff, bc = 0;
#pragma unroll
            for (int c = 0; c < 8; c++) {
                if (!((used >> c) & 1)) {
                    bool bet = (sc[c] > bv) || (sc[c] == bv && ci[c] < bi);
                    if (bet) { bv = sc[c]; bi = ci[c]; bc = c; }
                }
            }
            used |= 1u << bc; w4[s4] = bv; id4[s4] = bi;
        }
        if (lane == 0) {
            float e1 = expf(w4[1] - w4[0]);
            float e2 = expf(w4[2] - w4[0]);
            float e3 = expf(w4[3] - w4[0]);
            float ss = 1.f + e1 + e2 + e3;
            const int base = t * (NSEC * 4) + n * 4;
            g_w[base + 0] = 1.f / ss; g_ix[base + 0] = id4[0];
            g_w[base + 1] = e1 / ss;  g_ix[base + 1] = id4[1];
            g_w[base + 2] = e2 / ss;  g_ix[base + 2] = id4[2];
            g_w[base + 3] = e3 / ss;  g_ix[base + 3] = id4[3];
        }
    }
}

// ---------------------------------------------------------------------------
// k3: knowledge gather + matvec + sector mix + proj + residual + LayerNorm
// ---------------------------------------------------------------------------
__global__ __launch_bounds__(128) void k3_output(
    const float* __restrict__ knowledge, const float* __restrict__ Wo,
    const float* __restrict__ bo, const float* __restrict__ gamma,
    const float* __restrict__ beta, float* __restrict__ out)
{
    const int t = blockIdx.x, tid = threadIdx.x;
    const int lane = tid & 31, wid = tid >> 5;

    __shared__ float q[KDIM];
    __shared__ float sd[NSEC];
    __shared__ float fpart[4][VDIM];
    __shared__ float fin[VDIM];
    __shared__ float rs[4], rs2[4];
    __shared__ float mv[2];

    if (tid < KDIM) q[tid] = g_tq[t * KDIM + tid];
    if (tid < NSEC) sd[tid] = out[(size_t)NTOK * EDIM + t * NSEC + tid];
    __syncthreads();

    float facc = 0.f;
#pragma unroll
    for (int n = 0; n < NSEC; n++) {
        const int p = t * (NSEC * 4) + n * 4 + wid;
        const float wgt = g_w[p];
        const int   mi  = g_ix[p];
        const float* kn = knowledge + ((size_t)n * MTOT + mi) * (KDIM * VDIM);
        float r = 0.f;
#pragma unroll
        for (int d = 0; d < KDIM; d++)
            r += q[d] * kn[d * VDIM + lane];
        facc += sd[n] * wgt * r;
    }
    fpart[wid][lane] = facc;
    __syncthreads();
    if (tid < VDIM)
        fin[tid] = fpart[0][tid] + fpart[1][tid] + fpart[2][tid] + fpart[3][tid];
    __syncthreads();

    float4 accv = *(const float4*)&bo[tid * 4];
#pragma unroll
    for (int v = 0; v < VDIM; v++) {
        float fv = fin[v];
        float4 wv = *(const float4*)&Wo[v * EDIM + tid * 4];
        accv.x += fv * wv.x; accv.y += fv * wv.y;
        accv.z += fv * wv.z; accv.w += fv * wv.w;
    }
    float4 xv = *(const float4*)&g_xe[(size_t)t * EDIM + tid * 4];
    float4 h;
    h.x = xv.x + accv.x; h.y = xv.y + accv.y;
    h.z = xv.z + accv.z; h.w = xv.w + accv.w;

    float s  = h.x + h.y + h.z + h.w;
    float s2 = h.x*h.x + h.y*h.y + h.z*h.z + h.w*h.w;
#pragma unroll
    for (int o = 16; o > 0; o >>= 1) {
        s  += __shfl_xor_sync(0xffffffffu, s,  o);
        s2 += __shfl_xor_sync(0xffffffffu, s2, o);
    }
    if (lane == 0) { rs[wid] = s; rs2[wid] = s2; }
    __syncthreads();
    if (tid == 0) {
        float S  = rs[0] + rs[1] + rs[2] + rs[3];
        float S2 = rs2[0] + rs2[1] + rs2[2] + rs2[3];
        float mu  = S / (float)EDIM;
        float var = S2 / (float)EDIM - mu * mu;
        mv[0] = mu; mv[1] = rsqrtf(var + 1e-5f);
    }
    __syncthreads();
    const float mu = mv[0], rstd = mv[1];

    float4 gv = *(const float4*)&gamma[tid * 4];
    float4 bv = *(const float4*)&beta[tid * 4];
    float4 ov;
    ov.x = (h.x - mu) * rstd * gv.x + bv.x;
    ov.y = (h.y - mu) * rstd * gv.y + bv.y;
    ov.z = (h.z - mu) * rstd * gv.z + bv.z;
    ov.w = (h.w - mu) * rstd * gv.w + bv.w;
    *(float4*)&out[(size_t)t * EDIM + tid * 4] = ov;
}

// ---------------------------------------------------------------------------
extern "C" void kernel_launch(void* const* d_in, const int* in_sizes, int n_in,
                              void* d_out, int out_size)
{
    const int off = (n_in >= 12 && in_sizes[1] == 1) ? 1 : 0;

    const int*   x     = (const int*)  d_in[0];
    const float* emb   = (const float*)d_in[1 + off];
    const float* skeys = (const float*)d_in[2 + off];
    const float* mkeys = (const float*)d_in[3 + off];
    const float* knowl = (const float*)d_in[4 + off];
    const float* Wq    = (const float*)d_in[5 + off];
    const float* bq    = (const float*)d_in[6 + off];
    const float* Wo    = (const float*)d_in[7 + off];
    const float* bo    = (const float*)d_in[8 + off];
    const float* gamma = (const float*)d_in[9 + off];
    const float* beta  = (const float*)d_in[10 + off];
    float* out = (float*)d_out;
    (void)out_size;

    cudaFuncSetAttribute(k2_scores,
                         cudaFuncAttributeMaxDynamicSharedMemorySize, SMEM2);
    cudaFuncSetAttribute(k1b_tq,
                         cudaFuncAttributeMaxDynamicSharedMemorySize,
                         (EDIM * KDIM + 32 * XSTR) * 4);

    k1_embed<<<NTOK, 128>>>(x, emb, skeys, out + (size_t)NTOK * EDIM);
    mkb_conv<<<4096, 256>>>(mkeys);
    k1b_tq  <<<64, 256, (EDIM * KDIM + 32 * XSTR) * 4>>>(Wq, bq);
    k2_scores<<<dim3(16, 8), 256, SMEM2>>>(mkeys);
    k3_output<<<NTOK, 128>>>(knowl, Wo, bo, gamma, beta, out);
}

// round 8
// speedup vs baseline: 1.3042x; 1.2431x over previous
#include <cuda_runtime.h>
#include <cuda_bf16.h>
#include <cstdint>
#include <cstddef>

// ---------------------------------------------------------------------------
// HierarchicalMemoryWorker — int8 mma.sync (m16n8k32) candidate GEMM
//  + streaming top-8 + exact fp32 rerank.
// R8: K=32 per mma halves tensor/LDSM/ALU instruction stream vs bf16 k16.
// T=2048 tokens, E=512, N=8 sectors, M=2048, KD=VD=32, top-4
// ---------------------------------------------------------------------------

#define NTOK 2048
#define EDIM 512
#define NSEC 8
#define MTOT 2048
#define KDIM 32
#define VDIM 32

// ---- k2 smem layout ----
#define SA8_BYTES (128 * 512)              // A: 128 rows x 512B int8, swizzled
#define SB8_BYTES (128 * 128)              // B stage: 128 rows x 128B int8
#define NSTAGE    4
#define SS_OFF    (SA8_BYTES + NSTAGE * SB8_BYTES)   // 131072
#define SS_STRIDE 136                      // score row stride (bf16 elems)
#define SMS_OFF   (SS_OFF + 128 * SS_STRIDE * 2)     // 165888
#define SMEM2     (SMS_OFF + 512 + 16)               // 166416

// ---- device scratch (no allocation allowed) ----
__device__ float g_xe[NTOK * EDIM];
__device__ float g_tq[NTOK * KDIM];
__device__ float g_w [NTOK * NSEC * 4];
__device__ int   g_ix[NTOK * NSEC * 4];
__device__ __align__(16) int8_t g_xe8[NTOK * EDIM];          // 1 MB
__device__ __align__(16) int8_t g_mk8[NSEC * MTOT * EDIM];   // 8 MB
__device__ float g_ms[NSEC * MTOT];                          // per-row step

// ---- helpers ----
__device__ __forceinline__ uint32_t smem_u32(const void* p) {
    uint32_t a;
    asm("{ .reg .u64 t; cvta.to.shared.u64 t, %1; cvt.u32.u64 %0, t; }"
        : "=r"(a) : "l"(p));
    return a;
}
#define CP16(d, s) asm volatile("cp.async.ca.shared.global [%0], [%1], 16;" :: "r"(d), "l"(s))
#define CPCOMMIT() asm volatile("cp.async.commit_group;" ::: "memory")
#define CPWAIT1()  asm volatile("cp.async.wait_group 1;" ::: "memory")
#define CPWAIT0()  asm volatile("cp.async.wait_group 0;" ::: "memory")

#define LDM_X4(r0, r1, r2, r3, a) \
    asm volatile("ldmatrix.sync.aligned.m8n8.x4.shared.b16 {%0,%1,%2,%3}, [%4];" \
        : "=r"(r0), "=r"(r1), "=r"(r2), "=r"(r3) : "r"(a))

#define IMMA16832(c0, c1, c2, c3, a0, a1, a2, a3, b0, b1) \
    asm volatile("mma.sync.aligned.m16n8k32.row.col.s32.s8.s8.s32 " \
        "{%0,%1,%2,%3}, {%4,%5,%6,%7}, {%8,%9}, {%0,%1,%2,%3};" \
        : "+r"(c0), "+r"(c1), "+r"(c2), "+r"(c3) \
        : "r"(a0), "r"(a1), "r"(a2), "r"(a3), "r"(b0), "r"(b1))

// ---------------------------------------------------------------------------
// k1: embed gather + sector softmax + fp32 + int8 x_emb
// ---------------------------------------------------------------------------
__global__ __launch_bounds__(128) void k1_embed(
    const int* __restrict__ x, const float* __restrict__ emb,
    const float* __restrict__ skeys, float* __restrict__ outSD)
{
    const int t = blockIdx.x, tid = threadIdx.x;
    const int lane = tid & 31, wid = tid >> 5;
    __shared__ float sred[NSEC][4];
    __shared__ float smax[4];

    const int xi = x[t];
    float4 ev = *(const float4*)&emb[(size_t)xi * EDIM + tid * 4];
    *(float4*)&g_xe[(size_t)t * EDIM + tid * 4] = ev;

    float am = fmaxf(fmaxf(fabsf(ev.x), fabsf(ev.y)),
                     fmaxf(fabsf(ev.z), fabsf(ev.w)));
    float p[NSEC];
#pragma unroll
    for (int n = 0; n < NSEC; n++) {
        float4 kv = *(const float4*)&skeys[n * EDIM + tid * 4];
        p[n] = ev.x*kv.x + ev.y*kv.y + ev.z*kv.z + ev.w*kv.w;
    }
#pragma unroll
    for (int o = 16; o > 0; o >>= 1) {
        am = fmaxf(am, __shfl_xor_sync(0xffffffffu, am, o));
#pragma unroll
        for (int n = 0; n < NSEC; n++)
            p[n] += __shfl_xor_sync(0xffffffffu, p[n], o);
    }
    if (lane == 0) {
        smax[wid] = am;
#pragma unroll
        for (int n = 0; n < NSEC; n++) sred[n][wid] = p[n];
    }
    __syncthreads();
    {
        float amax = fmaxf(fmaxf(smax[0], smax[1]), fmaxf(smax[2], smax[3]));
        float inv = 127.f / amax;
        int q0 = __float2int_rn(ev.x * inv), q1 = __float2int_rn(ev.y * inv);
        int q2 = __float2int_rn(ev.z * inv), q3 = __float2int_rn(ev.w * inv);
        uint32_t pk = (uint32_t)(q0 & 0xff) | ((uint32_t)(q1 & 0xff) << 8)
                    | ((uint32_t)(q2 & 0xff) << 16) | ((uint32_t)(q3 & 0xff) << 24);
        *(uint32_t*)&g_xe8[(size_t)t * EDIM + tid * 4] = pk;
    }
    if (tid == 0) {
        float s[NSEC], mx = -1e30f, sum = 0.f;
#pragma unroll
        for (int n = 0; n < NSEC; n++) {
            s[n] = sred[n][0] + sred[n][1] + sred[n][2] + sred[n][3];
            mx = fmaxf(mx, s[n]);
        }
#pragma unroll
        for (int n = 0; n < NSEC; n++) { s[n] = expf(s[n] - mx); sum += s[n]; }
#pragma unroll
        for (int n = 0; n < NSEC; n++) outSD[t * NSEC + n] = s[n] / sum;
    }
}

// ---------------------------------------------------------------------------
// mkb8: memory_keys fp32 -> int8 rows + per-row step (grid 16384, block 128)
// ---------------------------------------------------------------------------
__global__ __launch_bounds__(128) void mkb8_conv(const float* __restrict__ mkeys)
{
    const int r = blockIdx.x, tid = threadIdx.x;
    const int lane = tid & 31, wid = tid >> 5;
    __shared__ float sm8[4];

    float4 v = *(const float4*)&mkeys[(size_t)r * EDIM + tid * 4];
    float am = fmaxf(fmaxf(fabsf(v.x), fabsf(v.y)),
                     fmaxf(fabsf(v.z), fabsf(v.w)));
#pragma unroll
    for (int o = 16; o > 0; o >>= 1)
        am = fmaxf(am, __shfl_xor_sync(0xffffffffu, am, o));
    if (lane == 0) sm8[wid] = am;
    __syncthreads();
    float amax = fmaxf(fmaxf(sm8[0], sm8[1]), fmaxf(sm8[2], sm8[3]));
    float inv = 127.f / amax;
    int q0 = __float2int_rn(v.x * inv), q1 = __float2int_rn(v.y * inv);
    int q2 = __float2int_rn(v.z * inv), q3 = __float2int_rn(v.w * inv);
    uint32_t pk = (uint32_t)(q0 & 0xff) | ((uint32_t)(q1 & 0xff) << 8)
                | ((uint32_t)(q2 & 0xff) << 16) | ((uint32_t)(q3 & 0xff) << 24);
    *(uint32_t*)&g_mk8[(size_t)r * EDIM + tid * 4] = pk;
    if (tid == 0) g_ms[r] = amax / 127.f;
}

// ---------------------------------------------------------------------------
// k1b: token query GEMM  tq[T,32] = xe[T,512] @ Wq[512,32] + bq
// ---------------------------------------------------------------------------
#define XSTR 68
__global__ __launch_bounds__(256) void k1b_tq(
    const float* __restrict__ Wq, const float* __restrict__ bq)
{
    extern __shared__ float s1b[];
    float* sWq = s1b;
    float* sxe = s1b + EDIM * KDIM;
    const int tid = threadIdx.x, tb = blockIdx.x * 32;
    const int row = tid & 31, h = tid >> 5;

    const float4* Wq4 = (const float4*)Wq;
#pragma unroll
    for (int i = 0; i < 16; i++)
        ((float4*)sWq)[i * 256 + tid] = Wq4[i * 256 + tid];

    float4 acc = *(const float4*)&bq[h * 4];
    for (int kc = 0; kc < EDIM; kc += 64) {
        __syncthreads();
        {
            const int lr = tid >> 3, lk = (tid & 7) * 8;
            const float* src = &g_xe[(size_t)(tb + lr) * EDIM + kc + lk];
            float4 a = *(const float4*)src, b = *(const float4*)(src + 4);
            float* d = &sxe[lr * XSTR + lk];
            d[0]=a.x; d[1]=a.y; d[2]=a.z; d[3]=a.w;
            d[4]=b.x; d[5]=b.y; d[6]=b.z; d[7]=b.w;
        }
        __syncthreads();
#pragma unroll 8
        for (int k = 0; k < 64; k++) {
            float a = sxe[row * XSTR + k];
            float4 wv = *(const float4*)&sWq[(kc + k) * KDIM + h * 4];
            acc.x += a * wv.x; acc.y += a * wv.y;
            acc.z += a * wv.z; acc.w += a * wv.w;
        }
    }
    *(float4*)&g_tq[(size_t)(tb + row) * KDIM + h * 4] = acc;
}

// ---------------------------------------------------------------------------
// k2: int8 mma score GEMM + streaming top-8 + exact fp32 rerank
// grid (16, 8), 256 threads = 8 warps (2 tokHalf x 4 memQuarter), 64x32 tiles
// ---------------------------------------------------------------------------
__global__ __launch_bounds__(256, 1) void k2_scores(const float* __restrict__ mkeys)
{
    extern __shared__ unsigned char sm2[];
    __nv_bfloat16* sS = (__nv_bfloat16*)(sm2 + SS_OFF);
    float* smS = (float*)(sm2 + SMS_OFF);

    const int tid = threadIdx.x, wid = tid >> 5, lane = tid & 31;
    const int tt = blockIdx.x, n = blockIdx.y, tb = tt * 128;
    const int warpM = wid & 1, warpN = wid >> 1;

    const uint32_t aAddr = smem_u32(sm2);
    const uint32_t bAddr0 = aAddr + SA8_BYTES;

    // ---- A: 128 rows x 512B int8 -> swizzled smem (c16 ^= r&7, low3) ----
    {
        const int8_t* Asrc = g_xe8 + (size_t)tb * EDIM;
#pragma unroll
        for (int it = 0; it < 16; it++) {
            int idx = it * 256 + tid;       // 0..4095
            int r = idx >> 5, c = idx & 31; // 32 x 16B per row
            CP16(aAddr + (r << 9) + ((c ^ (r & 7)) << 4),
                 Asrc + (size_t)r * EDIM + c * 16);
        }
        CPCOMMIT();
    }

    const int8_t* Bn = g_mk8 + (size_t)n * MTOT * EDIM;
    // stage ck (0..63): m-chunk ck>>2 (128 rows), k-part ck&3 (128 int8)
    auto issueB = [&](int ck) {
        const int chunk = ck >> 2, kp = ck & 3;
        const int8_t* src = Bn + (size_t)(chunk * 128) * EDIM + kp * 128;
        const uint32_t dst = bAddr0 + (ck & 3 | ((ck & 4) << 0)) * 0; // placeholder
        const uint32_t d0 = bAddr0 + (ck % NSTAGE) * SB8_BYTES;
        (void)dst;
#pragma unroll
        for (int it = 0; it < 4; it++) {
            int idx = it * 256 + tid;       // 0..1023
            int r = idx >> 3, c = idx & 7;  // 8 x 16B per row
            CP16(d0 + (r << 7) + ((c ^ (r & 7)) << 4),
                 src + (size_t)r * EDIM + c * 16);
        }
        CPCOMMIT();
    };
    issueB(0);
    issueB(1);

    // top-8 state (tid < 128 owns token tb+tid)
    float vt[8]; int ixt[8];
#pragma unroll
    for (int i = 0; i < 8; i++) { vt[i] = -3e38f; ixt[i] = 0; }

    int acc[4][4][4];
#pragma unroll
    for (int i = 0; i < 4; i++)
#pragma unroll
        for (int j = 0; j < 4; j++)
#pragma unroll
            for (int r = 0; r < 4; r++) acc[i][j][r] = 0;

    // ldmatrix lane constants
    const int xr7  = lane & 7;
    const int aRowL = warpM * 64 + (lane & 15);
    const int aHi   = lane >> 4;
    const int bRowL = warpN * 32 + (lane & 7) + ((lane >> 4) << 3);
    const int bHalf = (lane >> 3) & 1;

    uint32_t fa[2][4][4], fb[2][4][2];

    // s in 0..3 selects k32 within the stage's 128-k window
    auto loadFrags = [&](int buf, int ck, int s) {
        const uint32_t bBuf = bAddr0 + (ck % NSTAGE) * SB8_BYTES;
        const int kp = ck & 3;
#pragma unroll
        for (int i = 0; i < 4; i++) {
            int c16 = kp * 8 + s * 2 + aHi;
            uint32_t ad = aAddr + ((aRowL + i * 16) << 9) + ((c16 ^ xr7) << 4);
            LDM_X4(fa[buf][i][0], fa[buf][i][1], fa[buf][i][2], fa[buf][i][3], ad);
        }
#pragma unroll
        for (int jp = 0; jp < 2; jp++) {
            int c16 = s * 2 + bHalf;
            uint32_t bd = bBuf + ((bRowL + jp * 16) << 7) + ((c16 ^ xr7) << 4);
            LDM_X4(fb[buf][jp*2][0], fb[buf][jp*2][1],
                   fb[buf][jp*2+1][0], fb[buf][jp*2+1][1], bd);
        }
    };

    for (int ck = 0; ck < 64; ck++) {
        if (ck == 63) { CPWAIT0(); } else { CPWAIT1(); }
        __syncthreads();
        if (ck + 2 < 64) issueB(ck + 2);
        if ((ck & 3) == 0 && tid < 128)
            smS[tid] = g_ms[n * MTOT + (ck >> 2) * 128 + tid];

        loadFrags(0, ck, 0);
#pragma unroll
        for (int step = 0; step < 4; step++) {
            const int cur = step & 1, nxt = cur ^ 1;
            if (step < 3) loadFrags(nxt, ck, step + 1);
#pragma unroll
            for (int i = 0; i < 4; i++)
#pragma unroll
                for (int j = 0; j < 4; j++)
                    IMMA16832(acc[i][j][0], acc[i][j][1], acc[i][j][2], acc[i][j][3],
                              fa[cur][i][0], fa[cur][i][1], fa[cur][i][2], fa[cur][i][3],
                              fb[cur][j][0], fb[cur][j][1]);
        }

        if ((ck & 3) == 3) {
            // ---- epilogue: scale by per-memory step, dump bf16, scan ----
            const int row0 = warpM * 64 + (lane >> 2);
            const int col0 = warpN * 32 + (lane & 3) * 2;
#pragma unroll
            for (int i = 0; i < 4; i++)
#pragma unroll
                for (int j = 0; j < 4; j++) {
                    float s0 = smS[col0 + j * 8];
                    float s1 = smS[col0 + j * 8 + 1];
                    __nv_bfloat162 lo = __floats2bfloat162_rn(
                        __int2float_rn(acc[i][j][0]) * s0,
                        __int2float_rn(acc[i][j][1]) * s1);
                    __nv_bfloat162 hi = __floats2bfloat162_rn(
                        __int2float_rn(acc[i][j][2]) * s0,
                        __int2float_rn(acc[i][j][3]) * s1);
                    *(uint32_t*)&sS[(row0 + i * 16) * SS_STRIDE + col0 + j * 8] =
                        *(uint32_t*)&lo;
                    *(uint32_t*)&sS[(row0 + i * 16 + 8) * SS_STRIDE + col0 + j * 8] =
                        *(uint32_t*)&hi;
                    acc[i][j][0] = acc[i][j][1] = acc[i][j][2] = acc[i][j][3] = 0;
                }
            __syncthreads();
            if (tid < 128) {
                const int mbase = (ck >> 2) * 128;
                const __nv_bfloat16* srow = sS + tid * SS_STRIDE;
#pragma unroll 2
                for (int c0 = 0; c0 < 128; c0 += 8) {
                    uint4 u = *(const uint4*)(srow + c0);
                    const __nv_bfloat162* hp = (const __nv_bfloat162*)&u;
#pragma unroll
                    for (int p = 0; p < 4; p++) {
                        float f0 = __bfloat162float(__low2bfloat16(hp[p]));
                        float f1 = __bfloat162float(__high2bfloat16(hp[p]));
#pragma unroll
                        for (int h = 0; h < 2; h++) {
                            float sv = h ? f1 : f0;
                            if (sv > vt[7]) {
                                vt[7] = sv; ixt[7] = mbase + c0 + p * 2 + h;
#pragma unroll
                                for (int q = 7; q > 0; q--) {
                                    if (vt[q] > vt[q-1]) {
                                        float a2 = vt[q]; vt[q] = vt[q-1]; vt[q-1] = a2;
                                        int b2 = ixt[q]; ixt[q] = ixt[q-1]; ixt[q-1] = b2;
                                    }
                                }
                            }
                        }
                    }
                }
            }
        }
    }

    __syncthreads();
    int* scand = (int*)sS;
    if (tid < 128)
#pragma unroll
        for (int c = 0; c < 8; c++) scand[tid * 8 + c] = ixt[c];
    __syncthreads();

    // ---- exact fp32 rerank: 8 warps x 16 tokens, lane-split over E ----
    for (int ti = 0; ti < 16; ti++) {
        const int tl = wid * 16 + ti, t = tb + tl;
        const float* xr = g_xe + (size_t)t * EDIM + lane * 16;
        float4 x0 = *(const float4*)xr,       x1 = *(const float4*)(xr + 4);
        float4 x2 = *(const float4*)(xr + 8), x3 = *(const float4*)(xr + 12);
        float sc[8]; int ci[8];
#pragma unroll
        for (int c = 0; c < 8; c++) {
            ci[c] = scand[tl * 8 + c];
            const float* mr =
                mkeys + ((size_t)n * MTOT + ci[c]) * EDIM + lane * 16;
            float4 m0 = *(const float4*)mr,       m1 = *(const float4*)(mr + 4);
            float4 m2 = *(const float4*)(mr + 8), m3 = *(const float4*)(mr + 12);
            float d =            x0.x*m0.x;  d = fmaf(x0.y, m0.y, d);
            d = fmaf(x0.z, m0.z, d); d = fmaf(x0.w, m0.w, d);
            d = fmaf(x1.x, m1.x, d); d = fmaf(x1.y, m1.y, d);
            d = fmaf(x1.z, m1.z, d); d = fmaf(x1.w, m1.w, d);
            d = fmaf(x2.x, m2.x, d); d = fmaf(x2.y, m2.y, d);
            d = fmaf(x2.z, m2.z, d); d = fmaf(x2.w, m2.w, d);
            d = fmaf(x3.x, m3.x, d); d = fmaf(x3.y, m3.y, d);
            d = fmaf(x3.z, m3.z, d); d = fmaf(x3.w, m3.w, d);
#pragma unroll
            for (int o = 16; o > 0; o >>= 1)
                d += __shfl_xor_sync(0xffffffffu, d, o);
            sc[c] = d;
        }
        unsigned used = 0;
        float w4[4]; int id4[4];
#pragma unroll
        for (int s4 = 0; s4 < 4; s4++) {
            float bv = -3e38f; int bi = 0x7fffffff, bc = 0;
#pragma unroll
            for (int c = 0; c < 8; c++) {
                if (!((used >> c) & 1)) {
                    bool bet = (sc[c] > bv) || (sc[c] == bv && ci[c] < bi);
                    if (bet) { bv = sc[c]; bi = ci[c]; bc = c; }
                }
            }
            used |= 1u << bc; w4[s4] = bv; id4[s4] = bi;
        }
        if (lane == 0) {
            float e1 = expf(w4[1] - w4[0]);
            float e2 = expf(w4[2] - w4[0]);
            float e3 = expf(w4[3] - w4[0]);
            float ss = 1.f + e1 + e2 + e3;
            const int base = t * (NSEC * 4) + n * 4;
            g_w[base + 0] = 1.f / ss; g_ix[base + 0] = id4[0];
            g_w[base + 1] = e1 / ss;  g_ix[base + 1] = id4[1];
            g_w[base + 2] = e2 / ss;  g_ix[base + 2] = id4[2];
            g_w[base + 3] = e3 / ss;  g_ix[base + 3] = id4[3];
        }
    }
}

// ---------------------------------------------------------------------------
// k3: knowledge gather + matvec + sector mix + proj + residual + LayerNorm
// ---------------------------------------------------------------------------
__global__ __launch_bounds__(128) void k3_output(
    const float* __restrict__ knowledge, const float* __restrict__ Wo,
    const float* __restrict__ bo, const float* __restrict__ gamma,
    const float* __restrict__ beta, float* __restrict__ out)
{
    const int t = blockIdx.x, tid = threadIdx.x;
    const int lane = tid & 31, wid = tid >> 5;

    __shared__ float q[KDIM];
    __shared__ float sd[NSEC];
    __shared__ float fpart[4][VDIM];
    __shared__ float fin[VDIM];
    __shared__ float rs[4], rs2[4];
    __shared__ float mv[2];

    if (tid < KDIM) q[tid] = g_tq[t * KDIM + tid];
    if (tid < NSEC) sd[tid] = out[(size_t)NTOK * EDIM + t * NSEC + tid];
    __syncthreads();

    float facc = 0.f;
#pragma unroll
    for (int n = 0; n < NSEC; n++) {
        const int p = t * (NSEC * 4) + n * 4 + wid;
        const float wgt = g_w[p];
        const int   mi  = g_ix[p];
        const float* kn = knowledge + ((size_t)n * MTOT + mi) * (KDIM * VDIM);
        float r = 0.f;
#pragma unroll
        for (int d = 0; d < KDIM; d++)
            r += q[d] * kn[d * VDIM + lane];
        facc += sd[n] * wgt * r;
    }
    fpart[wid][lane] = facc;
    __syncthreads();
    if (tid < VDIM)
        fin[tid] = fpart[0][tid] + fpart[1][tid] + fpart[2][tid] + fpart[3][tid];
    __syncthreads();

    float4 accv = *(const float4*)&bo[tid * 4];
#pragma unroll
    for (int v = 0; v < VDIM; v++) {
        float fv = fin[v];
        float4 wv = *(const float4*)&Wo[v * EDIM + tid * 4];
        accv.x += fv * wv.x; accv.y += fv * wv.y;
        accv.z += fv * wv.z; accv.w += fv * wv.w;
    }
    float4 xv = *(const float4*)&g_xe[(size_t)t * EDIM + tid * 4];
    float4 h;
    h.x = xv.x + accv.x; h.y = xv.y + accv.y;
    h.z = xv.z + accv.z; h.w = xv.w + accv.w;

    float s  = h.x + h.y + h.z + h.w;
    float s2 = h.x*h.x + h.y*h.y + h.z*h.z + h.w*h.w;
#pragma unroll
    for (int o = 16; o > 0; o >>= 1) {
        s  += __shfl_xor_sync(0xffffffffu, s,  o);
        s2 += __shfl_xor_sync(0xffffffffu, s2, o);
    }
    if (lane == 0) { rs[wid] = s; rs2[wid] = s2; }
    __syncthreads();
    if (tid == 0) {
        float S  = rs[0] + rs[1] + rs[2] + rs[3];
        float S2 = rs2[0] + rs2[1] + rs2[2] + rs2[3];
        float mu  = S / (float)EDIM;
        float var = S2 / (float)EDIM - mu * mu;
        mv[0] = mu; mv[1] = rsqrtf(var + 1e-5f);
    }
    __syncthreads();
    const float mu = mv[0], rstd = mv[1];

    float4 gv = *(const float4*)&gamma[tid * 4];
    float4 bv = *(const float4*)&beta[tid * 4];
    float4 ov;
    ov.x = (h.x - mu) * rstd * gv.x + bv.x;
    ov.y = (h.y - mu) * rstd * gv.y + bv.y;
    ov.z = (h.z - mu) * rstd * gv.z + bv.z;
    ov.w = (h.w - mu) * rstd * gv.w + bv.w;
    *(float4*)&out[(size_t)t * EDIM + tid * 4] = ov;
}

// ---------------------------------------------------------------------------
extern "C" void kernel_launch(void* const* d_in, const int* in_sizes, int n_in,
                              void* d_out, int out_size)
{
    const int off = (n_in >= 12 && in_sizes[1] == 1) ? 1 : 0;

    const int*   x     = (const int*)  d_in[0];
    const float* emb   = (const float*)d_in[1 + off];
    const float* skeys = (const float*)d_in[2 + off];
    const float* mkeys = (const float*)d_in[3 + off];
    const float* knowl = (const float*)d_in[4 + off];
    const float* Wq    = (const float*)d_in[5 + off];
    const float* bq    = (const float*)d_in[6 + off];
    const float* Wo    = (const float*)d_in[7 + off];
    const float* bo    = (const float*)d_in[8 + off];
    const float* gamma = (const float*)d_in[9 + off];
    const float* beta  = (const float*)d_in[10 + off];
    float* out = (float*)d_out;
    (void)out_size;

    cudaFuncSetAttribute(k2_scores,
                         cudaFuncAttributeMaxDynamicSharedMemorySize, SMEM2);
    cudaFuncSetAttribute(k1b_tq,
                         cudaFuncAttributeMaxDynamicSharedMemorySize,
                         (EDIM * KDIM + 32 * XSTR) * 4);

    k1_embed <<<NTOK, 128>>>(x, emb, skeys, out + (size_t)NTOK * EDIM);
    mkb8_conv<<<NSEC * MTOT, 128>>>(mkeys);
    k1b_tq   <<<64, 256, (EDIM * KDIM + 32 * XSTR) * 4>>>(Wq, bq);
    k2_scores<<<dim3(16, 8), 256, SMEM2>>>(mkeys);
    k3_output<<<NTOK, 128>>>(knowl, Wo, bo, gamma, beta, out);
}